// round 4
// baseline (speedup 1.0000x reference)
#include <cuda_runtime.h>
#include <math.h>

#define BB 4
#define NN 512
#define HH 64
#define NH 4
#define DD 16
#define SCALE 0.25f      // 1/sqrt(16)
#define LN_EPS 1e-5f
#define NEGV  -1e9f
#define TI 8             // query rows per attn block

// Scratch (allocation-free: __device__ globals)
__device__ float g_T[BB*NN*HH];
__device__ float g_Q[BB*NN*HH];
__device__ float g_K[BB*NN*HH];
__device__ float g_V[BB*NN*HH];
__device__ float g_qw5[BB*NN*NH];
__device__ float g_qb5[BB*NN*NH];

// ---------------------------------------------------------------------------
// Kernel 1: node projections. 8 rows per block, 64 threads (one per out col).
// ---------------------------------------------------------------------------
__global__ void proj_kernel(const float* __restrict__ x,
    const float* __restrict__ W1w, const float* __restrict__ W1b,
    const float* __restrict__ W2w, const float* __restrict__ W2b,
    const float* __restrict__ W3w, const float* __restrict__ W3b,
    const float* __restrict__ W4w, const float* __restrict__ W4b,
    const float* __restrict__ W5w, const float* __restrict__ W5b)
{
    const int t = threadIdx.x;          // 0..63 output column
    const int row0 = blockIdx.x * 8;    // global row index (b*N+n)

    __shared__ float sx[8][64];
    __shared__ float sq[8][64];

    #pragma unroll
    for (int r = 0; r < 8; r++) sx[r][t] = x[(row0 + r)*HH + t];
    __syncthreads();

    float a1[8], a2[8], a3[8], a4[8];
    #pragma unroll
    for (int r = 0; r < 8; r++) { a1[r]=0.f; a2[r]=0.f; a3[r]=0.f; a4[r]=0.f; }

    #pragma unroll 8
    for (int k = 0; k < 64; k++) {
        const float w1 = W1w[k*64 + t];
        const float w2 = W2w[k*64 + t];
        const float w3 = W3w[k*64 + t];
        const float w4 = W4w[k*64 + t];
        #pragma unroll
        for (int r = 0; r < 8; r++) {
            const float xk = sx[r][k];
            a1[r] = fmaf(xk, w1, a1[r]);
            a2[r] = fmaf(xk, w2, a2[r]);
            a3[r] = fmaf(xk, w3, a3[r]);
            a4[r] = fmaf(xk, w4, a4[r]);
        }
    }

    const float b1 = W1b[t], b2 = W2b[t], b3 = W3b[t], b4 = W4b[t];
    #pragma unroll
    for (int r = 0; r < 8; r++) {
        const float q = a3[r] + b3;
        g_T[(row0 + r)*HH + t] = a1[r] + b1;
        g_V[(row0 + r)*HH + t] = a2[r] + b2;
        g_Q[(row0 + r)*HH + t] = q;
        g_K[(row0 + r)*HH + t] = a4[r] + b4;
        sq[r][t] = q;
    }
    __syncthreads();

    // qw5/qb5: edge-term scalars per (row, head)
    if (t < 32) {
        const int r = t >> 2, h = t & 3;
        float sw = 0.f, sb = 0.f;
        #pragma unroll
        for (int d = 0; d < 16; d++) {
            const float q = sq[r][h*16 + d];
            sw = fmaf(q, W5w[h*16 + d], sw);
            sb = fmaf(q, W5b[h*16 + d], sb);
        }
        g_qw5[(row0 + r)*NH + h] = sw;
        g_qb5[(row0 + r)*NH + h] = sb;
    }
}

// ---------------------------------------------------------------------------
// Kernel 2: fused scores + mask + softmax + attn*V + residual + LayerNorm.
// One block per (b, TI query rows). 512 threads. Dynamic smem (~86 KB).
// ---------------------------------------------------------------------------
#define SM_FLOATS (TI*NH*NN + TI*HH + TI*NH + TI*NH + 8*TI*HH + TI*HH)
#define SM_BYTES  (SM_FLOATS * 4)

__global__ __launch_bounds__(512)
void attn_kernel(const float* __restrict__ x,
                 const int*   __restrict__ adj,
                 const float* __restrict__ ef,
                 const float* __restrict__ lng,
                 const float* __restrict__ lnb,
                 float* __restrict__ out)
{
    extern __shared__ float smem[];
    float* s_sc  = smem;                   // [TI*NH][NN] scores -> probs
    float* s_q   = s_sc + TI*NH*NN;        // TI*HH
    float* s_qw  = s_q  + TI*HH;           // TI*NH
    float* s_qb  = s_qw + TI*NH;           // TI*NH
    float* s_red = s_qb + TI*NH;           // [8][TI*HH]
    float* s_y   = s_red + 8*TI*HH;        // TI*HH

    const int tid = threadIdx.x;                  // 0..511
    const int b   = blockIdx.x / (NN / TI);
    const int i0  = (blockIdx.x % (NN / TI)) * TI;

    if (tid < TI*HH) s_q[tid] = g_Q[(b*NN + i0)*HH + tid];
    if (tid < TI*NH) {
        s_qw[tid] = g_qw5[(b*NN + i0)*NH + tid];
        s_qb[tid] = g_qb5[(b*NN + i0)*NH + tid];
    }
    __syncthreads();

    // ---- Phase 1: scores. thread j computes TI*NH (i,h) scores. ----
    {
        const int j = tid;
        const float* Krow = &g_K[(b*NN + j)*HH];
        float ev[TI]; int av[TI];
        #pragma unroll
        for (int i = 0; i < TI; i++) {
            const long base = (long)(b*NN + i0 + i)*NN + j;
            ev[i] = ef[base];
            av[i] = adj[base];
        }
        #pragma unroll
        for (int h = 0; h < NH; h++) {
            const float4 k0 = *(const float4*)(Krow + h*16 + 0);
            const float4 k1 = *(const float4*)(Krow + h*16 + 4);
            const float4 k2 = *(const float4*)(Krow + h*16 + 8);
            const float4 k3 = *(const float4*)(Krow + h*16 + 12);
            #pragma unroll
            for (int i = 0; i < TI; i++) {
                const float* q = &s_q[i*HH + h*16];
                float dot =
                    k0.x*q[0]  + k0.y*q[1]  + k0.z*q[2]  + k0.w*q[3]
                  + k1.x*q[4]  + k1.y*q[5]  + k1.z*q[6]  + k1.w*q[7]
                  + k2.x*q[8]  + k2.y*q[9]  + k2.z*q[10] + k2.w*q[11]
                  + k3.x*q[12] + k3.y*q[13] + k3.z*q[14] + k3.w*q[15];
                const float sc = av[i]
                    ? (dot + ev[i]*s_qw[i*NH + h] + s_qb[i*NH + h]) * SCALE
                    : NEGV;
                s_sc[(i*NH + h)*NN + j] = sc;
            }
        }
    }
    __syncthreads();

    // ---- Phase 2: softmax. 32 units over 16 warps: warp w does u=w, w+16.
    //      Lane l owns 16 consecutive j (float4-vectorized, register-resident).
    {
        const int w = tid >> 5, lane = tid & 31;
        #pragma unroll
        for (int uu = 0; uu < 2; uu++) {
            float* row = &s_sc[(w + 16*uu)*NN + lane*16];
            float4 p0 = *(float4*)(row + 0);
            float4 p1 = *(float4*)(row + 4);
            float4 p2 = *(float4*)(row + 8);
            float4 p3 = *(float4*)(row + 12);
            float m = fmaxf(fmaxf(fmaxf(p0.x,p0.y),fmaxf(p0.z,p0.w)),
                      fmaxf(fmaxf(fmaxf(p1.x,p1.y),fmaxf(p1.z,p1.w)),
                      fmaxf(fmaxf(fmaxf(p2.x,p2.y),fmaxf(p2.z,p2.w)),
                            fmaxf(fmaxf(p3.x,p3.y),fmaxf(p3.z,p3.w)))));
            #pragma unroll
            for (int o = 16; o; o >>= 1) m = fmaxf(m, __shfl_xor_sync(0xffffffffu, m, o));
            p0.x=__expf(p0.x-m); p0.y=__expf(p0.y-m); p0.z=__expf(p0.z-m); p0.w=__expf(p0.w-m);
            p1.x=__expf(p1.x-m); p1.y=__expf(p1.y-m); p1.z=__expf(p1.z-m); p1.w=__expf(p1.w-m);
            p2.x=__expf(p2.x-m); p2.y=__expf(p2.y-m); p2.z=__expf(p2.z-m); p2.w=__expf(p2.w-m);
            p3.x=__expf(p3.x-m); p3.y=__expf(p3.y-m); p3.z=__expf(p3.z-m); p3.w=__expf(p3.w-m);
            float sum = (p0.x+p0.y+p0.z+p0.w) + (p1.x+p1.y+p1.z+p1.w)
                      + (p2.x+p2.y+p2.z+p2.w) + (p3.x+p3.y+p3.z+p3.w);
            #pragma unroll
            for (int o = 16; o; o >>= 1) sum += __shfl_xor_sync(0xffffffffu, sum, o);
            const float inv = 1.f / sum;
            p0.x*=inv; p0.y*=inv; p0.z*=inv; p0.w*=inv;
            p1.x*=inv; p1.y*=inv; p1.z*=inv; p1.w*=inv;
            p2.x*=inv; p2.y*=inv; p2.z*=inv; p2.w*=inv;
            p3.x*=inv; p3.y*=inv; p3.z*=inv; p3.w*=inv;
            *(float4*)(row + 0)  = p0;
            *(float4*)(row + 4)  = p1;
            *(float4*)(row + 8)  = p2;
            *(float4*)(row + 12) = p3;
        }
    }
    __syncthreads();

    // ---- Phase 3: msg = P @ V. thread = (slice of j, output col c).
    //      P loaded as float4 over j (broadcast across lanes sharing h).
    {
        const int slice = tid >> 6;   // 0..7
        const int c     = tid & 63;   // h*16+d
        const int h     = c >> 4;
        float acc[TI];
        #pragma unroll
        for (int i = 0; i < TI; i++) acc[i] = 0.f;
        const float* Vb = &g_V[(long)b*NN*HH];
        #pragma unroll
        for (int js = 0; js < 16; js++) {
            const int jx = slice*64 + js*4;
            const float v0 = Vb[(jx+0)*HH + c];
            const float v1 = Vb[(jx+1)*HH + c];
            const float v2 = Vb[(jx+2)*HH + c];
            const float v3 = Vb[(jx+3)*HH + c];
            #pragma unroll
            for (int i = 0; i < TI; i++) {
                const float4 p = *(const float4*)&s_sc[(i*NH + h)*NN + jx];
                acc[i] = fmaf(p.x, v0, acc[i]);
                acc[i] = fmaf(p.y, v1, acc[i]);
                acc[i] = fmaf(p.z, v2, acc[i]);
                acc[i] = fmaf(p.w, v3, acc[i]);
            }
        }
        #pragma unroll
        for (int i = 0; i < TI; i++)
            s_red[(slice*TI + i)*HH + c] = acc[i];
    }
    __syncthreads();

    // ---- Phase 3b: reduce slices + residual. tid covers TI*HH = 512. ----
    {
        const int i = tid >> 6, c = tid & 63;
        float m = 0.f;
        #pragma unroll
        for (int s = 0; s < 8; s++) m += s_red[(s*TI + i)*HH + c];
        const long r = (long)(b*NN + i0 + i)*HH + c;
        s_y[i*HH + c] = x[r] + g_T[r] + m;
    }
    __syncthreads();

    // ---- Phase 4: LayerNorm. warp w handles row i=w (TI*32 = 256 threads). -
    if (tid < TI*32) {
        const int i = tid >> 5, l = tid & 31;
        const float y0 = s_y[i*HH + l];
        const float y1 = s_y[i*HH + l + 32];
        float s  = y0 + y1;
        float sq = y0*y0 + y1*y1;
        #pragma unroll
        for (int o = 16; o; o >>= 1) {
            s  += __shfl_xor_sync(0xffffffffu, s,  o);
            sq += __shfl_xor_sync(0xffffffffu, sq, o);
        }
        const float mean = s * (1.f/64.f);
        const float var  = sq * (1.f/64.f) - mean*mean;
        const float rs   = rsqrtf(var + LN_EPS);
        float* op = &out[(long)(b*NN + i0 + i)*HH];
        op[l]      = (y0 - mean)*rs*lng[l]      + lnb[l];
        op[l + 32] = (y1 - mean)*rs*lng[l + 32] + lnb[l + 32];
    }
}

// ---------------------------------------------------------------------------
extern "C" void kernel_launch(void* const* d_in, const int* in_sizes, int n_in,
                              void* d_out, int out_size)
{
    const float* x   = (const float*)d_in[0];
    const int*   adj = (const int*)  d_in[1];
    const float* ef  = (const float*)d_in[2];
    const float* W1w = (const float*)d_in[3];
    const float* W1b = (const float*)d_in[4];
    const float* W2w = (const float*)d_in[5];
    const float* W2b = (const float*)d_in[6];
    const float* W3w = (const float*)d_in[7];
    const float* W3b = (const float*)d_in[8];
    const float* W4w = (const float*)d_in[9];
    const float* W4b = (const float*)d_in[10];
    const float* W5w = (const float*)d_in[11];
    const float* W5b = (const float*)d_in[12];
    const float* lng = (const float*)d_in[13];
    const float* lnb = (const float*)d_in[14];

    cudaFuncSetAttribute(attn_kernel,
                         cudaFuncAttributeMaxDynamicSharedMemorySize, SM_BYTES);

    proj_kernel<<<BB*NN/8, 64>>>(x, W1w, W1b, W2w, W2b, W3w, W3b,
                                 W4w, W4b, W5w, W5b);
    attn_kernel<<<BB*NN/TI, 512, SM_BYTES>>>(x, adj, ef, lng, lnb,
                                             (float*)d_out);
}

// round 5
// speedup vs baseline: 1.2035x; 1.2035x over previous
#include <cuda_runtime.h>
#include <math.h>

#define BB 4
#define NN 512
#define HH 64
#define NH 4
#define DD 16
#define SCALE 0.25f      // 1/sqrt(16)
#define LN_EPS 1e-5f
#define NEGV  -1e9f
#define TI 8             // query rows per attn block

// Scratch (allocation-free: __device__ globals)
__device__ float g_T [BB*NN*HH];
__device__ float g_Q [BB*NN*HH];
__device__ float g_Kt[BB*HH*NN];   // K transposed: [b][hd][j]
__device__ float g_V [BB*NN*HH];
__device__ float g_qw5[BB*NN*NH];
__device__ float g_qb5[BB*NN*NH];

// ---------------------------------------------------------------------------
// Kernel 1: node projections. 8 rows per block, 64 threads (one per out col).
// K is written transposed (thread owns 8 consecutive nodes for its column).
// ---------------------------------------------------------------------------
__global__ void proj_kernel(const float* __restrict__ x,
    const float* __restrict__ W1w, const float* __restrict__ W1b,
    const float* __restrict__ W2w, const float* __restrict__ W2b,
    const float* __restrict__ W3w, const float* __restrict__ W3b,
    const float* __restrict__ W4w, const float* __restrict__ W4b,
    const float* __restrict__ W5w, const float* __restrict__ W5b)
{
    const int t = threadIdx.x;          // 0..63 output column
    const int row0 = blockIdx.x * 8;    // global row index (b*N+n)

    __shared__ float sx[8][64];
    __shared__ float sq[8][64];

    #pragma unroll
    for (int r = 0; r < 8; r++) sx[r][t] = x[(row0 + r)*HH + t];
    __syncthreads();

    float a1[8], a2[8], a3[8], a4[8];
    #pragma unroll
    for (int r = 0; r < 8; r++) { a1[r]=0.f; a2[r]=0.f; a3[r]=0.f; a4[r]=0.f; }

    #pragma unroll 8
    for (int k = 0; k < 64; k++) {
        const float w1 = W1w[k*64 + t];
        const float w2 = W2w[k*64 + t];
        const float w3 = W3w[k*64 + t];
        const float w4 = W4w[k*64 + t];
        #pragma unroll
        for (int r = 0; r < 8; r++) {
            const float xk = sx[r][k];
            a1[r] = fmaf(xk, w1, a1[r]);
            a2[r] = fmaf(xk, w2, a2[r]);
            a3[r] = fmaf(xk, w3, a3[r]);
            a4[r] = fmaf(xk, w4, a4[r]);
        }
    }

    const float b1 = W1b[t], b2 = W2b[t], b3 = W3b[t], b4 = W4b[t];
    #pragma unroll
    for (int r = 0; r < 8; r++) {
        const float q = a3[r] + b3;
        g_T[(row0 + r)*HH + t] = a1[r] + b1;
        g_V[(row0 + r)*HH + t] = a2[r] + b2;
        g_Q[(row0 + r)*HH + t] = q;
        sq[r][t] = q;
    }

    // K transposed: thread t owns column t, nodes n0..n0+7 (contiguous in Kt)
    {
        const int bq = row0 >> 9;          // / NN
        const int n0 = row0 & (NN - 1);
        float* kt = &g_Kt[((long)bq*HH + t)*NN + n0];
        float4 v0 = make_float4(a4[0]+b4, a4[1]+b4, a4[2]+b4, a4[3]+b4);
        float4 v1 = make_float4(a4[4]+b4, a4[5]+b4, a4[6]+b4, a4[7]+b4);
        *(float4*)(kt)     = v0;
        *(float4*)(kt + 4) = v1;
    }
    __syncthreads();

    // qw5/qb5: edge-term scalars per (row, head)
    if (t < 32) {
        const int r = t >> 2, h = t & 3;
        float sw = 0.f, sb = 0.f;
        #pragma unroll
        for (int d = 0; d < 16; d++) {
            const float q = sq[r][h*16 + d];
            sw = fmaf(q, W5w[h*16 + d], sw);
            sb = fmaf(q, W5b[h*16 + d], sb);
        }
        g_qw5[(row0 + r)*NH + h] = sw;
        g_qb5[(row0 + r)*NH + h] = sb;
    }
}

// ---------------------------------------------------------------------------
// Kernel 2: fused scores + mask + softmax + attn*V + residual + LayerNorm.
// One block per (b, TI query rows). 512 threads. Dynamic smem (~86 KB).
// ---------------------------------------------------------------------------
#define SM_FLOATS (TI*NH*NN + HH*TI + TI*NH + TI*NH + 8*TI*HH + TI*HH)
#define SM_BYTES  (SM_FLOATS * 4)

__global__ __launch_bounds__(512)
void attn_kernel(const float* __restrict__ x,
                 const int*   __restrict__ adj,
                 const float* __restrict__ ef,
                 const float* __restrict__ lng,
                 const float* __restrict__ lnb,
                 float* __restrict__ out)
{
    extern __shared__ float smem[];
    float* s_sc  = smem;                   // [TI*NH][NN] scores -> probs
    float* s_qt  = s_sc + TI*NH*NN;        // [HH][TI]  Q transposed
    float* s_qw  = s_qt + HH*TI;           // TI*NH
    float* s_qb  = s_qw + TI*NH;           // TI*NH
    float* s_red = s_qb + TI*NH;           // [8][TI*HH]
    float* s_y   = s_red + 8*TI*HH;        // TI*HH

    const int tid = threadIdx.x;                  // 0..511
    const int b   = blockIdx.x / (NN / TI);
    const int i0  = (blockIdx.x % (NN / TI)) * TI;

    // Stage Q transposed: s_qt[hd][i]
    {
        const int i = tid >> 6, hd = tid & 63;
        s_qt[hd*TI + i] = g_Q[(b*NN + i0 + i)*HH + hd];
    }
    if (tid < TI*NH) {
        s_qw[tid] = g_qw5[(b*NN + i0)*NH + tid];
        s_qb[tid] = g_qb5[(b*NN + i0)*NH + tid];
    }
    __syncthreads();

    // ---- Phase 1: scores. thread j streams Kt coalesced; 32 reg accums. ----
    {
        const int j = tid;
        const float* KtB = &g_Kt[(long)b*HH*NN];
        float ev[TI]; int av[TI];
        #pragma unroll
        for (int i = 0; i < TI; i++) {
            const long base = (long)(b*NN + i0 + i)*NN + j;
            ev[i] = ef[base];
            av[i] = adj[base];
        }
        float acc[NH][TI];
        #pragma unroll
        for (int h = 0; h < NH; h++)
            #pragma unroll
            for (int i = 0; i < TI; i++) acc[h][i] = 0.f;

        #pragma unroll
        for (int h = 0; h < NH; h++) {
            #pragma unroll
            for (int d = 0; d < DD; d++) {
                const int hd = h*DD + d;
                const float kt = KtB[hd*NN + j];           // coalesced LDG
                const float4 qa = *(const float4*)&s_qt[hd*TI];     // broadcast
                const float4 qb = *(const float4*)&s_qt[hd*TI + 4];
                acc[h][0] = fmaf(qa.x, kt, acc[h][0]);
                acc[h][1] = fmaf(qa.y, kt, acc[h][1]);
                acc[h][2] = fmaf(qa.z, kt, acc[h][2]);
                acc[h][3] = fmaf(qa.w, kt, acc[h][3]);
                acc[h][4] = fmaf(qb.x, kt, acc[h][4]);
                acc[h][5] = fmaf(qb.y, kt, acc[h][5]);
                acc[h][6] = fmaf(qb.z, kt, acc[h][6]);
                acc[h][7] = fmaf(qb.w, kt, acc[h][7]);
            }
        }
        #pragma unroll
        for (int i = 0; i < TI; i++)
            #pragma unroll
            for (int h = 0; h < NH; h++) {
                const float sc = av[i]
                    ? (acc[h][i] + ev[i]*s_qw[i*NH + h] + s_qb[i*NH + h]) * SCALE
                    : NEGV;
                s_sc[(i*NH + h)*NN + j] = sc;
            }
    }
    __syncthreads();

    // ---- Phase 2: softmax. 32 units over 16 warps: warp w does u=w, w+16.
    //      Lane l owns 16 consecutive j (float4-vectorized, register-resident).
    {
        const int w = tid >> 5, lane = tid & 31;
        #pragma unroll
        for (int uu = 0; uu < 2; uu++) {
            float* row = &s_sc[(w + 16*uu)*NN + lane*16];
            float4 p0 = *(float4*)(row + 0);
            float4 p1 = *(float4*)(row + 4);
            float4 p2 = *(float4*)(row + 8);
            float4 p3 = *(float4*)(row + 12);
            float m = fmaxf(fmaxf(fmaxf(p0.x,p0.y),fmaxf(p0.z,p0.w)),
                      fmaxf(fmaxf(fmaxf(p1.x,p1.y),fmaxf(p1.z,p1.w)),
                      fmaxf(fmaxf(fmaxf(p2.x,p2.y),fmaxf(p2.z,p2.w)),
                            fmaxf(fmaxf(p3.x,p3.y),fmaxf(p3.z,p3.w)))));
            #pragma unroll
            for (int o = 16; o; o >>= 1) m = fmaxf(m, __shfl_xor_sync(0xffffffffu, m, o));
            p0.x=__expf(p0.x-m); p0.y=__expf(p0.y-m); p0.z=__expf(p0.z-m); p0.w=__expf(p0.w-m);
            p1.x=__expf(p1.x-m); p1.y=__expf(p1.y-m); p1.z=__expf(p1.z-m); p1.w=__expf(p1.w-m);
            p2.x=__expf(p2.x-m); p2.y=__expf(p2.y-m); p2.z=__expf(p2.z-m); p2.w=__expf(p2.w-m);
            p3.x=__expf(p3.x-m); p3.y=__expf(p3.y-m); p3.z=__expf(p3.z-m); p3.w=__expf(p3.w-m);
            float sum = (p0.x+p0.y+p0.z+p0.w) + (p1.x+p1.y+p1.z+p1.w)
                      + (p2.x+p2.y+p2.z+p2.w) + (p3.x+p3.y+p3.z+p3.w);
            #pragma unroll
            for (int o = 16; o; o >>= 1) sum += __shfl_xor_sync(0xffffffffu, sum, o);
            const float inv = 1.f / sum;
            p0.x*=inv; p0.y*=inv; p0.z*=inv; p0.w*=inv;
            p1.x*=inv; p1.y*=inv; p1.z*=inv; p1.w*=inv;
            p2.x*=inv; p2.y*=inv; p2.z*=inv; p2.w*=inv;
            p3.x*=inv; p3.y*=inv; p3.z*=inv; p3.w*=inv;
            *(float4*)(row + 0)  = p0;
            *(float4*)(row + 4)  = p1;
            *(float4*)(row + 8)  = p2;
            *(float4*)(row + 12) = p3;
        }
    }
    __syncthreads();

    // ---- Phase 3: msg = P @ V. thread = (slice of j, output col c).
    {
        const int slice = tid >> 6;   // 0..7
        const int c     = tid & 63;   // h*16+d
        const int h     = c >> 4;
        float acc[TI];
        #pragma unroll
        for (int i = 0; i < TI; i++) acc[i] = 0.f;
        const float* Vb = &g_V[(long)b*NN*HH];
        #pragma unroll
        for (int js = 0; js < 16; js++) {
            const int jx = slice*64 + js*4;
            const float v0 = Vb[(jx+0)*HH + c];
            const float v1 = Vb[(jx+1)*HH + c];
            const float v2 = Vb[(jx+2)*HH + c];
            const float v3 = Vb[(jx+3)*HH + c];
            #pragma unroll
            for (int i = 0; i < TI; i++) {
                const float4 p = *(const float4*)&s_sc[(i*NH + h)*NN + jx];
                acc[i] = fmaf(p.x, v0, acc[i]);
                acc[i] = fmaf(p.y, v1, acc[i]);
                acc[i] = fmaf(p.z, v2, acc[i]);
                acc[i] = fmaf(p.w, v3, acc[i]);
            }
        }
        #pragma unroll
        for (int i = 0; i < TI; i++)
            s_red[(slice*TI + i)*HH + c] = acc[i];
    }
    __syncthreads();

    // ---- Phase 3b: reduce slices + residual. tid covers TI*HH = 512. ----
    {
        const int i = tid >> 6, c = tid & 63;
        float m = 0.f;
        #pragma unroll
        for (int s = 0; s < 8; s++) m += s_red[(s*TI + i)*HH + c];
        const long r = (long)(b*NN + i0 + i)*HH + c;
        s_y[i*HH + c] = x[r] + g_T[r] + m;
    }
    __syncthreads();

    // ---- Phase 4: LayerNorm. warp w handles row i=w (TI*32 = 256 threads). -
    if (tid < TI*32) {
        const int i = tid >> 5, l = tid & 31;
        const float y0 = s_y[i*HH + l];
        const float y1 = s_y[i*HH + l + 32];
        float s  = y0 + y1;
        float sq = y0*y0 + y1*y1;
        #pragma unroll
        for (int o = 16; o; o >>= 1) {
            s  += __shfl_xor_sync(0xffffffffu, s,  o);
            sq += __shfl_xor_sync(0xffffffffu, sq, o);
        }
        const float mean = s * (1.f/64.f);
        const float var  = sq * (1.f/64.f) - mean*mean;
        const float rs   = rsqrtf(var + LN_EPS);
        float* op = &out[(long)(b*NN + i0 + i)*HH];
        op[l]      = (y0 - mean)*rs*lng[l]      + lnb[l];
        op[l + 32] = (y1 - mean)*rs*lng[l + 32] + lnb[l + 32];
    }
}

// ---------------------------------------------------------------------------
extern "C" void kernel_launch(void* const* d_in, const int* in_sizes, int n_in,
                              void* d_out, int out_size)
{
    const float* x   = (const float*)d_in[0];
    const int*   adj = (const int*)  d_in[1];
    const float* ef  = (const float*)d_in[2];
    const float* W1w = (const float*)d_in[3];
    const float* W1b = (const float*)d_in[4];
    const float* W2w = (const float*)d_in[5];
    const float* W2b = (const float*)d_in[6];
    const float* W3w = (const float*)d_in[7];
    const float* W3b = (const float*)d_in[8];
    const float* W4w = (const float*)d_in[9];
    const float* W4b = (const float*)d_in[10];
    const float* W5w = (const float*)d_in[11];
    const float* W5b = (const float*)d_in[12];
    const float* lng = (const float*)d_in[13];
    const float* lnb = (const float*)d_in[14];

    cudaFuncSetAttribute(attn_kernel,
                         cudaFuncAttributeMaxDynamicSharedMemorySize, SM_BYTES);

    proj_kernel<<<BB*NN/8, 64>>>(x, W1w, W1b, W2w, W2b, W3w, W3b,
                                 W4w, W4b, W5w, W5b);
    attn_kernel<<<BB*NN/TI, 512, SM_BYTES>>>(x, adj, ef, lng, lnb,
                                             (float*)d_out);
}